// round 6
// baseline (speedup 1.0000x reference)
#include <cuda_runtime.h>
#include <cuda_fp16.h>

#define NC   3144   // counties
#define TT   156    // time steps
#define TP   154    // predicted steps (T - p)
#define TPAD 160    // padded t dimension
#define NCELL 40    // TPAD/4 uint4 (fp16) cells per column
#define NJ   80     // TPAD/2 float4 base cells per column
#define NNZ  31440
#define CAP  128    // bucket capacity (Poisson(10), max ~35)
#define FIXN 16     // fixed unrolled nnz iterations (zero-padded)

#define SCAT_BLOCKS 123                 // ceil(NNZ/256)
#define COV_BLOCKS  13                  // ceil(NC/256)
#define NMB         50                  // ceil(NC/64)
#define NTC         10                  // TPAD/16
#define PREP_BLOCKS (NMB * NTC)         // 500

// ---- scratch (zero-initialized at load; meta slots >= cnt stay zero) ----
__device__ int    g_count[NC];
__device__ int4   g_meta[NC * CAP];     // {row, bv, av, hv}; pad slots = 0
__device__ float2 g_covb[NC];           // {ups@cov, zeta@cov}
__device__ uint4  g_csdh[NC * NCELL];   // 4x half2{cs,ds} per cell (4 t)
__device__ float4 g_base4[NC * NJ];     // {bc,bd,bc,bd} per 2 t

// ============================================================
// Kernel A: scatter (123) + cov (13) + prep (500) blocks.
// Prep: block = 64 counties x 16 t; thread = 1 county x 4 t.
// ============================================================
__global__ void prep_scatter_kernel(
    const float* __restrict__ C, const float* __restrict__ D,
    const float* __restrict__ M, const float* __restrict__ cov,
    const float* __restrict__ mu, const float* __restrict__ nu,
    const float* __restrict__ ups, const float* __restrict__ zeta,
    const float* __restrict__ bnz, const float* __restrict__ anz,
    const float* __restrict__ hnz, const int* __restrict__ rows,
    const int* __restrict__ cols)
{
    const int b  = blockIdx.x;
    const int tx = threadIdx.x;

    // ---------------- scatter ----------------
    if (b < SCAT_BLOCKS) {
        int k = b * 256 + tx;
        if (k < NNZ) {
            int c = cols[k];
            int slot = atomicAdd(&g_count[c], 1);
            if (slot < CAP)
                g_meta[c * CAP + slot] = make_int4(
                    rows[k], __float_as_int(bnz[k]),
                    __float_as_int(anz[k]), __float_as_int(hnz[k]));
        }
        return;
    }
    // ---------------- cov base ----------------
    if (b < SCAT_BLOCKS + COV_BLOCKS) {
        int m = (b - SCAT_BLOCKS) * 256 + tx;
        if (m < NC) {
            float a = 0.f, z = 0.f;
#pragma unroll
            for (int j = 0; j < 10; j++) {
                float cv = cov[j * NC + m];
                a += ups[j]  * cv;
                z += zeta[j] * cv;
            }
            g_covb[m] = make_float2(a, z);
        }
        return;
    }

    // ---------------- prep ----------------
    __shared__ uint4  s_h[64][4];       // fp16 csd cells
    __shared__ float4 s_b[64][8];       // base cells

    const int pb   = b - SCAT_BLOCKS - COV_BLOCKS;
    const int mblk = pb % NMB, tcb = pb / NMB;
    const int ml_  = tx & 63, sub = tx >> 6;
    const int m0   = mblk * 64;
    const int m    = min(m0 + ml_, NC - 1);
    const int t0   = tcb * 16 + sub * 4;

    float muv[12], nuv[12];
#pragma unroll
    for (int i = 0; i < 12; i++) { muv[i] = mu[i]; nuv[i] = nu[i]; }

    // rotating "next" values: each t-level loaded once per thread
    float cn = C[t0 * NC + m];
    float dn = D[t0 * NC + m];
    float mn[6];
#pragma unroll
    for (int k = 0; k < 6; k++) mn[k] = M[(k * TT + t0) * NC + m];

    float cs[4], ds[4], bc[4], bd[4];
#pragma unroll
    for (int j = 0; j < 4; j++) {
        int tn = min(t0 + j + 1, TT - 1);   // t>=154 never reaches output
        float c0 = cn;  cn = C[tn * NC + m];
        float d0 = dn;  dn = D[tn * NC + m];
        cs[j] = c0 + cn;
        ds[j] = d0 + dn;
        float mc = 0.f, md = 0.f;
#pragma unroll
        for (int k = 0; k < 6; k++) {
            float v0 = mn[k];
            float v1 = M[(k * TT + tn) * NC + m];
            mn[k] = v1;
            mc += muv[k*2] * v0 + muv[k*2+1] * v1;
            md += nuv[k*2] * v0 + nuv[k*2+1] * v1;
        }
        bc[j] = mc;
        bd[j] = md;
    }

    uint4 cellh;
    __half2* hp = reinterpret_cast<__half2*>(&cellh);
#pragma unroll
    for (int j = 0; j < 4; j++) hp[j] = __floats2half2_rn(cs[j], ds[j]);
    s_h[ml_][sub] = cellh;
    s_b[ml_][sub * 2    ] = make_float4(bc[0], bd[0], bc[1], bd[1]);
    s_b[ml_][sub * 2 + 1] = make_float4(bc[2], bd[2], bc[3], bd[3]);
    __syncthreads();

    // coalesced writeout: 64B runs (csdh), 128B runs (base)
    {
        int ml = tx >> 2, sl = tx & 3;
        if (m0 + ml < NC)
            g_csdh[(m0 + ml) * NCELL + tcb * 4 + sl] = s_h[ml][sl];
    }
#pragma unroll
    for (int i = 0; i < 2; i++) {
        int idx = i * 256 + tx;            // 0..511
        int ml = idx >> 3, cl = idx & 7;
        if (m0 + ml < NC)
            g_base4[(m0 + ml) * NJ + tcb * 8 + cl] = s_b[ml][cl];
    }
}

// ============================================================
// Kernel B: gather. 393 blocks x 320 threads; thread = one
// (column, 4t-cell) task. Fixed FIXN=16 unrolled nnz loop
// (zero-padded meta), fp16 operand, fp32 accumulate.
// ============================================================
__global__ void __launch_bounds__(320) main_kernel(float* __restrict__ out)
{
    __shared__ int4   smeta[8][FIXN];
    __shared__ int    scnt[8];
    __shared__ float2 tile[TPAD][10];     // [t][m_local], padded

    const int tid  = threadIdx.x;
    const int m0   = blockIdx.x * 8;
    const int col  = tid / NCELL;         // 0..7
    const int cell = tid - col * NCELL;   // 0..39
    const int m    = m0 + col;

    if (tid < 8 * FIXN)
        smeta[tid >> 4][tid & 15] = g_meta[(m0 + (tid >> 4)) * CAP + (tid & 15)];
    if (tid < 8) {
        int c = g_count[m0 + tid];
        scnt[tid] = c;
        g_count[m0 + tid] = 0;            // re-arm for graph replay
    }
    __syncthreads();

    // base + covariate
    float accC[4], accD[4];
    {
        float2 cv = g_covb[m];
        float4 b0 = g_base4[m * NJ + 2 * cell];
        float4 b1 = g_base4[m * NJ + 2 * cell + 1];
        accC[0] = b0.x + cv.x;  accD[0] = b0.y + cv.y;
        accC[1] = b0.z + cv.x;  accD[1] = b0.w + cv.y;
        accC[2] = b1.x + cv.x;  accD[2] = b1.y + cv.y;
        accC[3] = b1.z + cv.x;  accD[3] = b1.w + cv.y;
    }

#pragma unroll 8
    for (int j = 0; j < FIXN; j++) {
        int4 md = smeta[col][j];          // LDS (<=2 distinct addrs/warp)
        uint4 v = g_csdh[md.x * NCELL + cell];
        float bv = __int_as_float(md.y);
        float av = __int_as_float(md.z);
        float hv = __int_as_float(md.w);
        const __half2* h = reinterpret_cast<const __half2*>(&v);
#pragma unroll
        for (int k = 0; k < 4; k++) {
            float2 p = __half22float2(h[k]);
            accC[k] += bv * p.x;
            accD[k] += hv * p.x + av * p.y;
        }
    }
    // rare tail: cnt > FIXN (~3% of columns)
    const int mycnt = scnt[col];
    for (int s = FIXN; s < mycnt; s++) {
        int4 md = g_meta[m * CAP + s];
        uint4 v = g_csdh[md.x * NCELL + cell];
        float bv = __int_as_float(md.y);
        float av = __int_as_float(md.z);
        float hv = __int_as_float(md.w);
        const __half2* h = reinterpret_cast<const __half2*>(&v);
#pragma unroll
        for (int k = 0; k < 4; k++) {
            float2 p = __half22float2(h[k]);
            accC[k] += bv * p.x;
            accD[k] += hv * p.x + av * p.y;
        }
    }

    // transpose through smem, coalesced stores
#pragma unroll
    for (int k = 0; k < 4; k++)
        tile[4 * cell + k][col] = make_float2(accC[k], accD[k]);
    __syncthreads();

#pragma unroll
    for (int i = 0; i < 4; i++) {
        int idx = i * 320 + tid;          // < 1280 = TPAD*8
        int t = idx >> 3, mo = idx & 7;
        if (t < TP) {
            float2 v = tile[t][mo];
            out[t        * NC + m0 + mo] = v.x;
            out[(TP + t) * NC + m0 + mo] = v.y;
        }
    }
}

// ============================================================
extern "C" void kernel_launch(void* const* d_in, const int* in_sizes, int n_in,
                              void* d_out, int out_size)
{
    const float* C    = (const float*)d_in[0];
    const float* D    = (const float*)d_in[1];
    const float* M    = (const float*)d_in[2];
    const float* cov  = (const float*)d_in[3];
    const float* bnz  = (const float*)d_in[4];
    const float* anz  = (const float*)d_in[5];
    const float* hnz  = (const float*)d_in[6];
    const float* mu   = (const float*)d_in[7];
    const float* nu   = (const float*)d_in[8];
    const float* ups  = (const float*)d_in[9];
    const float* zeta = (const float*)d_in[10];
    const int*   rows = (const int*)d_in[11];
    const int*   cols = (const int*)d_in[12];
    float* out = (float*)d_out;

    prep_scatter_kernel<<<SCAT_BLOCKS + COV_BLOCKS + PREP_BLOCKS, 256>>>(
        C, D, M, cov, mu, nu, ups, zeta, bnz, anz, hnz, rows, cols);

    main_kernel<<<NC / 8, 320>>>(out);
}